// round 3
// baseline (speedup 1.0000x reference)
#include <cuda_runtime.h>
#include <math.h>
#include <stdint.h>

#define Bm   64
#define Tm   512
#define Hm   512
#define Cm   64
#define NBLK 128
#define NTHR 256
#define SQ   260
#define SM_WORDS (128*SQ + 32*64)
#define SM_BYTES (SM_WORDS*4)
#define FC_SM_BYTES (128*SQ*4)

// Persistent scratch (static __device__ arrays: allowed; no runtime allocs)
__device__ float g_h1[2][2][Bm*Hm];
__device__ float g_c1[2][Bm*Hm];
__device__ float g_h2[2][2][Bm*Hm];
__device__ float g_c2[2][Bm*Hm];
__device__ float g_hist[2][Tm][Bm*Hm];
__device__ unsigned g_cnt = 0;
__device__ unsigned g_gen = 0;

__device__ __forceinline__ float4 ldcg4(const float* p) {
    return __ldcg((const float4*)p);
}
__device__ __forceinline__ void fma4(float s, const float4 v, float4& a) {
    a.x = fmaf(s, v.x, a.x); a.y = fmaf(s, v.y, a.y);
    a.z = fmaf(s, v.z, a.z); a.w = fmaf(s, v.w, a.w);
}
__device__ __forceinline__ float sigf(float x) { return 1.0f / (1.0f + expf(-x)); }

// Stage [64][512] row-major global -> smem transposed: sT[kq*SQ + i*64 + b] = src[b*512+4kq+i]
__device__ __forceinline__ void stage_T(const float* __restrict__ src,
                                        float* __restrict__ sT, int tid) {
#pragma unroll
    for (int it = 0; it < 32; ++it) {
        int id   = tid + NTHR * it;
        int lane = id & 31;
        int grp  = id >> 5;
        int kl   = lane & 7;
        int bg   = lane >> 3;
        int kq   = ((grp & 15) << 3) | kl;
        int b    = ((grp >> 4) << 2) | bg;
        float4 v = ldcg4(src + b * Hm + (kq << 2));
        float* p = sT + kq * SQ + b;
        p[0] = v.x; p[64] = v.y; p[128] = v.z; p[192] = v.w;
    }
}

// a0/a1 += W[j0/j1,:] . sT (batches 4*bq..4*bq+3), K=512
__device__ __forceinline__ void accum_pass(const float* __restrict__ W,
                                           const float* __restrict__ sT,
                                           int j0, int j1, int bq,
                                           float4& a0, float4& a1) {
    const float4* w0p = (const float4*)(W + j0 * Hm);
    const float4* w1p = (const float4*)(W + j1 * Hm);
    const float* hp = sT + (bq << 2);
#pragma unroll 4
    for (int kq = 0; kq < 128; ++kq) {
        float4 w0 = __ldg(w0p + kq);
        float4 w1 = __ldg(w1p + kq);
        const float* hq = hp + kq * SQ;
        float4 h0 = *(const float4*)(hq);
        float4 h1 = *(const float4*)(hq + 64);
        float4 h2 = *(const float4*)(hq + 128);
        float4 h3 = *(const float4*)(hq + 192);
        fma4(w0.x, h0, a0); fma4(w0.y, h1, a0); fma4(w0.z, h2, a0); fma4(w0.w, h3, a0);
        fma4(w1.x, h0, a1); fma4(w1.y, h1, a1); fma4(w1.z, h2, a1); fma4(w1.w, h3, a1);
    }
}

__device__ __forceinline__ void grid_barrier() {
    __threadfence();
    __syncthreads();
    if (threadIdx.x == 0) {
        unsigned genv = *((volatile unsigned*)&g_gen);
        unsigned arr = atomicAdd(&g_cnt, 1u);
        if (arr == NBLK - 1) {
            atomicExch(&g_cnt, 0u);
            __threadfence();
            atomicAdd(&g_gen, 1u);
        } else {
            while (*((volatile unsigned*)&g_gen) == genv) { __nanosleep(200); }
        }
        __threadfence();
    }
    __syncthreads();
}

extern "C" __global__ void __launch_bounds__(NTHR, 1)
lstm_persist(const float* __restrict__ x,
             const float* wih1, const float* whh1, const float* bih1, const float* bhh1,
             const float* wih2, const float* whh2, const float* bih2, const float* bhh2,
             const float* wih3, const float* whh3, const float* bih3, const float* bhh3,
             const float* wih4, const float* whh4, const float* bih4, const float* bhh4) {
    extern __shared__ float sm[];
    float* sT = sm;
    float* sg = sm + 128 * SQ;

    const int tid = threadIdx.x;
    const int dir = blockIdx.x & 1;
    const int gb  = blockIdx.x >> 1;
    const int hcb = gb << 3;

    const float* WIH1 = dir ? wih3 : wih1;
    const float* WHH1 = dir ? whh3 : whh1;
    const float* BIH1 = dir ? bih3 : bih1;
    const float* BHH1 = dir ? bhh3 : bhh1;
    const float* WIH2 = dir ? wih4 : wih2;
    const float* WHH2 = dir ? whh4 : whh2;
    const float* BIH2 = dir ? bih4 : bih2;
    const float* BHH2 = dir ? bhh4 : bhh2;

    // Zero persistent state every launch (deterministic across graph replays)
    {
        const int gt = blockIdx.x * NTHR + tid;
        const int stride = NBLK * NTHR;
        float* h1f = (float*)g_h1;
        float* h2f = (float*)g_h2;
        float* c1f = (float*)g_c1;
        float* c2f = (float*)g_c2;
        for (int i = gt; i < 2 * 2 * Bm * Hm; i += stride) { __stcg(&h1f[i], 0.0f); __stcg(&h2f[i], 0.0f); }
        for (int i = gt; i < 2 * Bm * Hm; i += stride)     { __stcg(&c1f[i], 0.0f); __stcg(&c2f[i], 0.0f); }
    }
    grid_barrier();

    const int bq = tid & 15;
    const int rp = tid >> 4;
    const int r0 = rp, r1 = rp + 16;
    const int j0 = ((r0 >> 3) << 9) + hcb + (r0 & 7);
    const int j1 = ((r1 >> 3) << 9) + hcb + (r1 & 7);
    const int b0 = bq << 2;

    const float bias1_0 = __ldg(BIH1 + j0) + __ldg(BHH1 + j0);
    const float bias1_1 = __ldg(BIH1 + j1) + __ldg(BHH1 + j1);
    const float bias2_0 = __ldg(BIH2 + j0) + __ldg(BHH2 + j0);
    const float bias2_1 = __ldg(BIH2 + j1) + __ldg(BHH2 + j1);
    const float xw0 = __ldg(WIH1 + j0);  // w_ih layer1 is [2048][1]
    const float xw1 = __ldg(WIH1 + j1);

    const int hcl0 = tid >> 6,         ab0 = tid & 63;
    const int hcl1 = (tid + 256) >> 6, ab1 = tid & 63;

    float* c1buf = g_c1[dir];
    float* c2buf = g_c2[dir];

#pragma unroll 1
    for (int t = 0; t < Tm; ++t) {
        const int cur = t & 1, nxt = cur ^ 1;
        const int te = dir ? (Tm - 1 - t) : t;

        // -------- cell 1 --------
        stage_T(g_h1[dir][cur], sT, tid);
        __syncthreads();

        float4 a0 = make_float4(bias1_0, bias1_0, bias1_0, bias1_0);
        float4 a1 = make_float4(bias1_1, bias1_1, bias1_1, bias1_1);
        {
            float4 xv = make_float4(__ldg(x + (b0 + 0) * Tm + te),
                                    __ldg(x + (b0 + 1) * Tm + te),
                                    __ldg(x + (b0 + 2) * Tm + te),
                                    __ldg(x + (b0 + 3) * Tm + te));
            fma4(xw0, xv, a0);
            fma4(xw1, xv, a1);
        }
        accum_pass(WHH1, sT, j0, j1, bq, a0, a1);

        *(float4*)(sg + r0 * 64 + b0) = a0;
        *(float4*)(sg + r1 * 64 + b0) = a1;
        __syncthreads();

        {
            float gi = sg[(0 * 8 + hcl0) * 64 + ab0];
            float gf = sg[(1 * 8 + hcl0) * 64 + ab0];
            float gg = sg[(2 * 8 + hcl0) * 64 + ab0];
            float go = sg[(3 * 8 + hcl0) * 64 + ab0];
            int idx = ab0 * Hm + hcb + hcl0;
            float cold = __ldcg(&c1buf[idx]);
            float cn = sigf(gf) * cold + sigf(gi) * tanhf(gg);
            __stcg(&c1buf[idx], cn);
            __stcg(&g_h1[dir][nxt][idx], sigf(go) * tanhf(cn));

            gi = sg[(0 * 8 + hcl1) * 64 + ab1];
            gf = sg[(1 * 8 + hcl1) * 64 + ab1];
            gg = sg[(2 * 8 + hcl1) * 64 + ab1];
            go = sg[(3 * 8 + hcl1) * 64 + ab1];
            idx = ab1 * Hm + hcb + hcl1;
            cold = __ldcg(&c1buf[idx]);
            cn = sigf(gf) * cold + sigf(gi) * tanhf(gg);
            __stcg(&c1buf[idx], cn);
            __stcg(&g_h1[dir][nxt][idx], sigf(go) * tanhf(cn));
        }
        grid_barrier();

        // -------- cell 2 (input = c1) --------
        stage_T(c1buf, sT, tid);
        __syncthreads();

        a0 = make_float4(bias2_0, bias2_0, bias2_0, bias2_0);
        a1 = make_float4(bias2_1, bias2_1, bias2_1, bias2_1);
        accum_pass(WIH2, sT, j0, j1, bq, a0, a1);
        __syncthreads();

        stage_T(g_h2[dir][cur], sT, tid);
        __syncthreads();
        accum_pass(WHH2, sT, j0, j1, bq, a0, a1);

        *(float4*)(sg + r0 * 64 + b0) = a0;
        *(float4*)(sg + r1 * 64 + b0) = a1;
        __syncthreads();

        {
            float gi = sg[(0 * 8 + hcl0) * 64 + ab0];
            float gf = sg[(1 * 8 + hcl0) * 64 + ab0];
            float gg = sg[(2 * 8 + hcl0) * 64 + ab0];
            float go = sg[(3 * 8 + hcl0) * 64 + ab0];
            int idx = ab0 * Hm + hcb + hcl0;
            float cold = __ldcg(&c2buf[idx]);
            float cn = sigf(gf) * cold + sigf(gi) * tanhf(gg);
            __stcg(&c2buf[idx], cn);
            __stcg(&g_h2[dir][nxt][idx], sigf(go) * tanhf(cn));
            g_hist[dir][t][idx] = cn;

            gi = sg[(0 * 8 + hcl1) * 64 + ab1];
            gf = sg[(1 * 8 + hcl1) * 64 + ab1];
            gg = sg[(2 * 8 + hcl1) * 64 + ab1];
            go = sg[(3 * 8 + hcl1) * 64 + ab1];
            idx = ab1 * Hm + hcb + hcl1;
            cold = __ldcg(&c2buf[idx]);
            cn = sigf(gf) * cold + sigf(gi) * tanhf(gg);
            __stcg(&c2buf[idx], cn);
            __stcg(&g_h2[dir][nxt][idx], sigf(go) * tanhf(cn));
            g_hist[dir][t][idx] = cn;
        }
        grid_barrier();
    }
}

// out[d][b][t][c] = dot(hist[d][t][b][:], W_d[c][:]) + bias_d[c]
extern "C" __global__ void __launch_bounds__(NTHR)
fc_kernel(const float* __restrict__ fcw, const float* __restrict__ fcb,
          const float* __restrict__ bfcw, const float* __restrict__ bfcb,
          float* __restrict__ out) {
    extern __shared__ float sm[];
    float* sT = sm;
    const int tid = threadIdx.x;
    const int d = blockIdx.x >> 9;
    const int t = blockIdx.x & 511;
    const float* W = d ? bfcw : fcw;     // [64][512]
    const float* bias = d ? bfcb : fcb;

    stage_T(W, sT, tid);
    __syncthreads();

    const float* hb = g_hist[d][t];
    const size_t obase = (size_t)d * Bm * Tm * Cm + (size_t)t * Cm;

#pragma unroll
    for (int tt = 0; tt < 4; ++tt) {
        int tile = tid + NTHR * tt;      // (b, c-quad)
        int b = tile >> 4;
        int c0 = (tile & 15) << 2;
        float4 acc = *(const float4*)(bias + c0);
        const float4* hq = (const float4*)(hb + b * Hm);
        const float* wq0 = sT + c0;
#pragma unroll 4
        for (int kq = 0; kq < 128; ++kq) {
            float4 h4 = __ldg(hq + kq);
            const float* wq = wq0 + kq * SQ;
            fma4(h4.x, *(const float4*)(wq), acc);
            fma4(h4.y, *(const float4*)(wq + 64), acc);
            fma4(h4.z, *(const float4*)(wq + 128), acc);
            fma4(h4.w, *(const float4*)(wq + 192), acc);
        }
        *(float4*)(out + obase + (size_t)b * Tm * Cm + c0) = acc;
    }
}

extern "C" void kernel_launch(void* const* d_in, const int* in_sizes, int n_in,
                              void* d_out, int out_size) {
    const float* x    = (const float*)d_in[0];
    const float* wih1 = (const float*)d_in[1];
    const float* whh1 = (const float*)d_in[2];
    const float* bih1 = (const float*)d_in[3];
    const float* bhh1 = (const float*)d_in[4];
    const float* wih2 = (const float*)d_in[5];
    const float* whh2 = (const float*)d_in[6];
    const float* bih2 = (const float*)d_in[7];
    const float* bhh2 = (const float*)d_in[8];
    const float* wih3 = (const float*)d_in[9];
    const float* whh3 = (const float*)d_in[10];
    const float* bih3 = (const float*)d_in[11];
    const float* bhh3 = (const float*)d_in[12];
    const float* wih4 = (const float*)d_in[13];
    const float* whh4 = (const float*)d_in[14];
    const float* bih4 = (const float*)d_in[15];
    const float* bhh4 = (const float*)d_in[16];
    const float* fcw  = (const float*)d_in[17];
    const float* fcb  = (const float*)d_in[18];
    const float* bfcw = (const float*)d_in[19];
    const float* bfcb = (const float*)d_in[20];

    static int attr_done = 0;
    if (!attr_done) {
        cudaFuncSetAttribute(lstm_persist, cudaFuncAttributeMaxDynamicSharedMemorySize, SM_BYTES);
        cudaFuncSetAttribute(fc_kernel, cudaFuncAttributeMaxDynamicSharedMemorySize, FC_SM_BYTES);
        attr_done = 1;
    }

    lstm_persist<<<NBLK, NTHR, SM_BYTES>>>(x,
        wih1, whh1, bih1, bhh1, wih2, whh2, bih2, bhh2,
        wih3, whh3, bih3, bhh3, wih4, whh4, bih4, bhh4);

    fc_kernel<<<2 * Tm, NTHR, FC_SM_BYTES>>>(fcw, fcb, bfcw, bfcb, (float*)d_out);
}